// round 4
// baseline (speedup 1.0000x reference)
#include <cuda_runtime.h>

#define NQ 21
#define NL 4
#define AD 18
#define NSTATE (1 << NQ)

// 16MB statevector scratch (device global: allocation-free).
static __device__ float2 g_psi[NSTATE];
static __device__ float  g_z[NQ];
static __device__ float  g_S;

// ---------- helpers ----------

__device__ __forceinline__ int sw(int i) {
    // nibble XOR swizzle: spreads stride-16 patterns across bank pairs
    return i ^ ((i >> 4) & 15);
}

__device__ __forceinline__ float2 cmul(float2 a, float2 b) {
    return make_float2(a.x * b.x - a.y * b.y, a.x * b.y + a.y * b.x);
}

// A*x + B*y (complex)
__device__ __forceinline__ float2 cmadd2(float2 A, float2 x, float2 B, float2 y) {
    float re = fmaf(A.x, x.x, fmaf(-A.y, x.y, fmaf(B.x, y.x, -B.y * y.y)));
    float im = fmaf(A.x, x.y, fmaf( A.y, x.x, fmaf(B.x, y.y,  B.y * y.x)));
    return make_float2(re, im);
}

// U = RZ(g) * RY(b) * RX(a)   (rotation order in reference: RX, then RY, then RZ)
__device__ void compute_U(const float* p, float2* U) {
    float sx, cx, sy, cy, sz, cz;
    sincosf(0.5f * p[0], &sx, &cx);
    sincosf(0.5f * p[1], &sy, &cy);
    sincosf(0.5f * p[2], &sz, &cz);
    // M1 = RY * RX
    float2 m00 = make_float2( cy * cx,  sy * sx);
    float2 m01 = make_float2(-sy * cx, -cy * sx);
    float2 m10 = make_float2( sy * cx, -cy * sx);
    float2 m11 = make_float2( cy * cx, -sy * sx);
    float2 ezm = make_float2(cz, -sz);   // e^{-i g/2}
    float2 ezp = make_float2(cz,  sz);   // e^{+i g/2}
    U[0] = cmul(ezm, m00);
    U[1] = cmul(ezm, m01);
    U[2] = cmul(ezp, m10);
    U[3] = cmul(ezp, m11);
}

// Apply two single-qubit gates on adjacent local bits (b, b+1) in one sweep.
// A acts on bit b, B acts on bit b+1. nquad = tile_size / 4.
__device__ __forceinline__ void pair_sweep(float2* s, int nquad, int b,
                                           const float2* Ap, const float2* Bp,
                                           int tid, int nthr) {
    float2 A0 = Ap[0], A1 = Ap[1], A2 = Ap[2], A3 = Ap[3];
    float2 B0 = Bp[0], B1 = Bp[1], B2 = Bp[2], B3 = Bp[3];
    for (int j = tid; j < nquad; j += nthr) {
        int i = ((j >> b) << (b + 2)) | (j & ((1 << b) - 1));
        int i0 = sw(i);
        int i1 = sw(i + (1 << b));
        int i2 = sw(i + (2 << b));
        int i3 = sw(i + (3 << b));
        float2 x00 = s[i0], x01 = s[i1], x10 = s[i2], x11 = s[i3];
        float2 y00 = cmadd2(A0, x00, A1, x01);
        float2 y01 = cmadd2(A2, x00, A3, x01);
        float2 y10 = cmadd2(A0, x10, A1, x11);
        float2 y11 = cmadd2(A2, x10, A3, x11);
        s[i0] = cmadd2(B0, y00, B1, y10);
        s[i2] = cmadd2(B2, y00, B3, y10);
        s[i1] = cmadd2(B0, y01, B1, y11);
        s[i3] = cmadd2(B2, y01, B3, y11);
    }
}

// ---------- pass H: local bits {0,1} U {11..20} ----------
// Rotations on global bits 11..20 (wires 9..0), then CNOT chain
// (gbit20->19, ..., 12->11) folded into the store permutation.
__global__ void __launch_bounds__(512) pass_h(const float* __restrict__ params,
                                              const float* __restrict__ state_in,
                                              int layer, int first, int do_cnot) {
    __shared__ float2 s[4096];
    __shared__ float2 sU[NQ][4];
    int tid = threadIdx.x;
    int c = blockIdx.x;  // chunk = global bits 2..10 (9 bits)

    if (tid < NQ) compute_U(params + layer * 63 + tid * 3, sU[tid]);

    if (first) {
        for (int v = tid; v < 4096; v += 512) {
            int g = (v & 3) | (c << 2) | ((v >> 2) << 11);
            s[sw(v)] = make_float2(state_in[g], 0.0f);
        }
    } else {
        for (int v = tid; v < 4096; v += 512) {
            int g = (v & 3) | (c << 2) | ((v >> 2) << 11);
            s[sw(v)] = g_psi[g];
        }
    }
    __syncthreads();

    // local bits 2..11 <-> global bits 11..20 <-> wires 9..0 : wire = 11 - localbit
#pragma unroll
    for (int pi = 0; pi < 5; ++pi) {
        int b = 2 + 2 * pi;
        pair_sweep(s, 1024, b, sU[11 - b], sU[10 - b], tid, 512);
        __syncthreads();
    }

    // Store with CNOT-chain permutation: local bits 2..10 get suffix-XOR (up to bit 11).
    for (int v = tid; v < 4096; v += 512) {
        int w = v;
        if (do_cnot) {
            int x = v;
            x ^= x >> 1; x ^= x >> 2; x ^= x >> 4; x ^= x >> 8;
            w = (v & ~0x7FC) | (x & 0x7FC);
        }
        int g = (w & 3) | (c << 2) | ((w >> 2) << 11);
        g_psi[g] = s[sw(v)];
    }
}

// ---------- pass L: local bits {0..10} U {20} ----------
// Rotations on global bits 0..10 (wires 20..10); CNOTs (11->10),(10->9)...(1->0)
// and the wrap (0->20) folded into the store permutation. Control gbit11 = chunk bit 0.
__global__ void __launch_bounds__(512) pass_l(const float* __restrict__ params, int layer) {
    __shared__ float2 s[4096];
    __shared__ float2 sU[NQ][4];
    int tid = threadIdx.x;
    int c = blockIdx.x;  // chunk = global bits 11..19 (9 bits)

    if (tid < NQ) compute_U(params + layer * 63 + tid * 3, sU[tid]);

    for (int v = tid; v < 4096; v += 512) {
        int g = (v & 0x7FF) | (c << 11) | ((v >> 11) << 20);
        s[sw(v)] = g_psi[g];
    }
    __syncthreads();

    // local bit b (0..10) <-> global bit b <-> wire 20-b
#pragma unroll
    for (int pi = 0; pi < 5; ++pi) {
        int b = 2 * pi;
        pair_sweep(s, 1024, b, sU[20 - b], sU[19 - b], tid, 512);
        __syncthreads();
    }
    {  // single rotation on local bit 10 (wire 10)
        float2 U0 = sU[10][0], U1 = sU[10][1], U2 = sU[10][2], U3 = sU[10][3];
        for (int j = tid; j < 2048; j += 512) {
            int i  = ((j >> 10) << 11) | (j & 1023);
            int i0 = sw(i), i1 = sw(i | 1024);
            float2 x0 = s[i0], x1 = s[i1];
            s[i0] = cmadd2(U0, x0, U1, x1);
            s[i1] = cmadd2(U2, x0, U3, x1);
        }
    }
    __syncthreads();

    // Permutation: low' = suffixXOR(bits0..10) ^ K (K = ctrl gbit11); bit20' ^= low'_0
    int K = (c & 1) ? 0x7FF : 0;
    for (int v = tid; v < 4096; v += 512) {
        int u = v & 0x7FF;
        int x = u;
        x ^= x >> 1; x ^= x >> 2; x ^= x >> 4; x ^= x >> 8;
        int low = x ^ K;
        int w = low | (((((v >> 11) ^ low) & 1)) << 11);
        int g = (w & 0x7FF) | (c << 11) | ((w >> 11) << 20);
        g_psi[g] = s[sw(v)];
    }
}

// ---------- final pass: layer-3 rotations on wires 10..20 + measurement ----------
__global__ void __launch_bounds__(512) pass_f(const float* __restrict__ params) {
    __shared__ float2 s[2048];
    __shared__ float2 sU[NQ][4];
    __shared__ float red[12];
    int tid = threadIdx.x;
    int c = blockIdx.x;  // chunk = global bits 11..20 (10 bits)

    if (tid < NQ) compute_U(params + 3 * 63 + tid * 3, sU[tid]);
    if (tid < 12) red[tid] = 0.0f;

    for (int v = tid; v < 2048; v += 512) s[sw(v)] = g_psi[v | (c << 11)];
    __syncthreads();

#pragma unroll
    for (int pi = 0; pi < 5; ++pi) {
        int b = 2 * pi;
        pair_sweep(s, 512, b, sU[20 - b], sU[19 - b], tid, 512);
        __syncthreads();
    }
    {  // single rotation on local bit 10 (wire 10)
        float2 U0 = sU[10][0], U1 = sU[10][1], U2 = sU[10][2], U3 = sU[10][3];
        for (int j = tid; j < 1024; j += 512) {
            int i0 = sw(j), i1 = sw(j | 1024);
            float2 x0 = s[i0], x1 = s[i1];
            s[i0] = cmadd2(U0, x0, U1, x1);
            s[i1] = cmadd2(U2, x0, U3, x1);
        }
    }
    __syncthreads();

    // acc[b] = sum m * (+1 if local bit b == 0 else -1), acc[11] = sum m
    float acc[12];
#pragma unroll
    for (int k = 0; k < 12; ++k) acc[k] = 0.0f;
    for (int v = tid; v < 2048; v += 512) {
        float2 a = s[sw(v)];
        float m = fmaf(a.x, a.x, a.y * a.y);
        acc[11] += m;
#pragma unroll
        for (int b = 0; b < 11; ++b) acc[b] += ((v >> b) & 1) ? -m : m;
    }
#pragma unroll
    for (int k = 0; k < 12; ++k) {
        float val = acc[k];
#pragma unroll
        for (int o = 16; o > 0; o >>= 1) val += __shfl_down_sync(0xffffffffu, val, o);
        if ((tid & 31) == 0) atomicAdd(&red[k], val);
    }
    __syncthreads();

    if (tid == 0) {
        float S = red[11];
        atomicAdd(&g_S, S);
        // wires 10..20 come from local bits: wire = 20 - b
#pragma unroll
        for (int b = 0; b < 11; ++b) atomicAdd(&g_z[20 - b], red[b]);
        // wires 0..9: global bit 20-q = chunk bit (9-q), fixed per block
#pragma unroll
        for (int q = 0; q < 10; ++q)
            atomicAdd(&g_z[q], ((c >> (9 - q)) & 1) ? -S : S);
    }
}

// ---------- tiny kernels ----------
__global__ void zero_acc() {
    int t = threadIdx.x;
    if (t < NQ) g_z[t] = 0.0f;
    if (t == NQ) g_S = 0.0f;
}

__global__ void head_kernel(const float* __restrict__ w, const float* __restrict__ b,
                            float* __restrict__ out) {
    if (threadIdx.x == 0) {
        float S = g_S;
        float inv = (S > 0.0f) ? (1.0f / S) : 0.0f;
        float meas[NQ];
        for (int q = 0; q < NQ; ++q) meas[q] = g_z[q] * inv;
        float logits[AD];
        float mx = -1e30f;
        for (int a = 0; a < AD; ++a) {
            float t = b[a];
            for (int q = 0; q < NQ; ++q) t = fmaf(w[a * NQ + q], meas[q], t);
            logits[a] = t;
            if (t > mx) mx = t;
        }
        float sum = 0.0f;
        for (int a = 0; a < AD; ++a) {
            float e = expf(logits[a] - mx);
            logits[a] = e;
            sum += e;
        }
        float is = 1.0f / sum;
        for (int a = 0; a < AD; ++a) out[a] = logits[a] * is;
    }
}

// ---------- launch ----------
extern "C" void kernel_launch(void* const* d_in, const int* in_sizes, int n_in,
                              void* d_out, int out_size) {
    const float* state  = (const float*)d_in[0];  // 2^21 float32
    const float* params = (const float*)d_in[1];  // 252 float32
    const float* hw     = (const float*)d_in[2];  // 18*21 float32
    const float* hb     = (const float*)d_in[3];  // 18 float32
    float* out = (float*)d_out;

    zero_acc<<<1, 32>>>();
    // layer 0
    pass_h<<<512, 512>>>(params, state, 0, 1, 1);
    pass_l<<<512, 512>>>(params, 0);
    // layer 1
    pass_h<<<512, 512>>>(params, state, 1, 0, 1);
    pass_l<<<512, 512>>>(params, 1);
    // layer 2
    pass_h<<<512, 512>>>(params, state, 2, 0, 1);
    pass_l<<<512, 512>>>(params, 2);
    // layer 3 (no entangler) + measurement
    pass_h<<<512, 512>>>(params, state, 3, 0, 0);
    pass_f<<<1024, 512>>>(params);
    head_kernel<<<1, 32>>>(hw, hb, out);
}

// round 5
// speedup vs baseline: 1.5581x; 1.5581x over previous
#include <cuda_runtime.h>

#define NQ 21
#define AD 18
#define NSTATE (1 << NQ)

typedef unsigned long long u64;

// 16MB statevector scratch, stored as packed complex: low 32 bits = re, high = im.
static __device__ u64   g_psi[NSTATE];
static __device__ float g_z[NQ];
static __device__ float g_S;

// ---------- packed f32x2 helpers ----------

__device__ __forceinline__ u64 pack2(float lo, float hi) {
    u64 d; asm("mov.b64 %0, {%1,%2};" : "=l"(d) : "f"(lo), "f"(hi)); return d;
}
__device__ __forceinline__ void unpack2(u64 d, float& lo, float& hi) {
    asm("mov.b64 {%0,%1}, %2;" : "=f"(lo), "=f"(hi) : "l"(d));
}
__device__ __forceinline__ u64 dswap(u64 d) {  // (re,im) -> (im,re)
    float lo, hi; unpack2(d, lo, hi); return pack2(hi, lo);
}
__device__ __forceinline__ u64 ffma2(u64 a, u64 b, u64 c) {
    u64 d; asm("fma.rn.f32x2 %0, %1, %2, %3;" : "=l"(d) : "l"(a), "l"(b), "l"(c)); return d;
}
__device__ __forceinline__ u64 fmul2(u64 a, u64 b) {
    u64 d; asm("mul.rn.f32x2 %0, %1, %2;" : "=l"(d) : "l"(a), "l"(b)); return d;
}

__device__ __forceinline__ float2 cmulc(float2 a, float2 b) {
    return make_float2(a.x * b.x - a.y * b.y, a.x * b.y + a.y * b.x);
}

// U = RZ(g)*RY(b)*RX(a); packed coeffs: for element E: (E.x,E.x), (-E.y,E.y).
// C[0..1]=U00, C[2..3]=U01, C[4..5]=U10, C[6..7]=U11
__device__ void compute_U(const float* p, u64* C) {
    float sx, cx, sy, cy, sz, cz;
    sincosf(0.5f * p[0], &sx, &cx);
    sincosf(0.5f * p[1], &sy, &cy);
    sincosf(0.5f * p[2], &sz, &cz);
    float2 m00 = make_float2( cy * cx,  sy * sx);
    float2 m01 = make_float2(-sy * cx, -cy * sx);
    float2 m10 = make_float2( sy * cx, -cy * sx);
    float2 m11 = make_float2( cy * cx, -sy * sx);
    float2 ezm = make_float2(cz, -sz), ezp = make_float2(cz, sz);
    float2 U0 = cmulc(ezm, m00), U1 = cmulc(ezm, m01);
    float2 U2 = cmulc(ezp, m10), U3 = cmulc(ezp, m11);
    C[0] = pack2(U0.x, U0.x); C[1] = pack2(-U0.y, U0.y);
    C[2] = pack2(U1.x, U1.x); C[3] = pack2(-U1.y, U1.y);
    C[4] = pack2(U2.x, U2.x); C[5] = pack2(-U2.y, U2.y);
    C[6] = pack2(U3.x, U3.x); C[7] = pack2(-U3.y, U3.y);
}

// Gate on register bit J: pairs (r, r^(1<<J)) within the 16-amp register file.
template<int J>
__device__ __forceinline__ void reg_gate(u64* a, const u64* C) {
    u64 c0 = C[0], c1 = C[1], c2 = C[2], c3 = C[3];
    u64 c4 = C[4], c5 = C[5], c6 = C[6], c7 = C[7];
#pragma unroll
    for (int r = 0; r < 16; ++r) {
        if (!(r & (1 << J))) {
            u64 x0 = a[r], x1 = a[r ^ (1 << J)];
            u64 s0 = dswap(x0), s1 = dswap(x1);
            a[r]            = ffma2(c0, x0, ffma2(c1, s0, ffma2(c2, x1, fmul2(c3, s1))));
            a[r ^ (1 << J)] = ffma2(c4, x0, ffma2(c5, s0, ffma2(c6, x1, fmul2(c7, s1))));
        }
    }
}

// Gate on lane bit k via shfl_xor. Each lane computes its own new amp:
// bit==0: out = U00*x + U01*p ; bit==1: out = U10*p + U11*x.
__device__ __forceinline__ void lane_gate(u64* a, int l, int k, const u64* C) {
    int bit = (l >> k) & 1;
    u64 d0 = bit ? C[6] : C[0];   // coeff of own amp
    u64 d1 = bit ? C[7] : C[1];
    u64 d2 = bit ? C[4] : C[2];   // coeff of partner amp
    u64 d3 = bit ? C[5] : C[3];
#pragma unroll
    for (int r = 0; r < 16; ++r) {
        u64 p = __shfl_xor_sync(0xffffffffu, a[r], 1 << k);
        a[r] = ffma2(d0, a[r], ffma2(d1, dswap(a[r]), ffma2(d2, p, fmul2(d3, dswap(p)))));
    }
}

// ---------- pass H: local bits v0,v1 -> g0,g1 ; v2..v11 -> g11..g20 ----------
// Rotations on wires 0..9 (g20..g11). CNOT chain (wires 0->1 .. 8->9) folded
// into the store address (suffix-XOR on v bits 2..10).
__global__ void __launch_bounds__(256) pass_h(const float* __restrict__ params,
                                              const float* __restrict__ state_in,
                                              int layer, int first, int do_cnot) {
    __shared__ u64 s[4096];
    __shared__ u64 sC[NQ][8];
    int tid = threadIdx.x;
    int l = tid & 31, w = tid >> 5;
    int c = blockIdx.x;  // chunk = g2..g10

    if (tid < NQ) compute_U(params + layer * 63 + tid * 3, sC[tid]);

    u64 a[16];
    // phase-1 mapping: v = l | (r<<5) | (w<<9)
    if (first) {
#pragma unroll
        for (int r = 0; r < 16; ++r) {
            int v = l | (r << 5) | (w << 9);
            int g = (v & 3) | (c << 2) | ((v >> 2) << 11);
            a[r] = pack2(state_in[g], 0.0f);
        }
    } else {
#pragma unroll
        for (int r = 0; r < 16; ++r) {
            int v = l | (r << 5) | (w << 9);
            int g = (v & 3) | (c << 2) | ((v >> 2) << 11);
            a[r] = g_psi[g];
        }
    }
    __syncthreads();  // sC ready

    // lane bits v2,v3,v4 -> g11,g12,g13 -> wires 9,8,7
    lane_gate(a, l, 2, sC[9]);
    lane_gate(a, l, 3, sC[8]);
    lane_gate(a, l, 4, sC[7]);
    // reg bits (v5..v8) -> g14..g17 -> wires 6,5,4,3
    reg_gate<0>(a, sC[6]);
    reg_gate<1>(a, sC[5]);
    reg_gate<2>(a, sC[4]);
    reg_gate<3>(a, sC[3]);

    // exchange: reg bits now cover v8..v11, warp bits cover v5..v7
#pragma unroll
    for (int r = 0; r < 16; ++r) s[l | (r << 5) | (w << 9)] = a[r];
    __syncthreads();
#pragma unroll
    for (int r = 0; r < 16; ++r) a[r] = s[l | (w << 5) | (r << 8)];

    // reg bits 1,2,3 -> v9,v10,v11 -> g18,g19,g20 -> wires 2,1,0
    reg_gate<1>(a, sC[2]);
    reg_gate<2>(a, sC[1]);
    reg_gate<3>(a, sC[0]);

    // store with CNOT-chain permutation on v bits 2..10
#pragma unroll
    for (int r = 0; r < 16; ++r) {
        int v = l | (w << 5) | (r << 8);
        int wv = v;
        if (do_cnot) {
            int x = v;
            x ^= x >> 1; x ^= x >> 2; x ^= x >> 4; x ^= x >> 8;
            wv = (v & ~0x7FC) | (x & 0x7FC);
        }
        int g = (wv & 3) | (c << 2) | ((wv >> 2) << 11);
        g_psi[g] = a[r];
    }
}

// ---------- pass L: local bits v0..v10 -> g0..g10 ; v11 -> g20 ----------
// Rotations on wires 10..20 (g10..g0). CNOTs (9->10 .. 19->20) + wrap (20->0)
// folded into the store address. Control g11 = chunk bit 0 (classical).
__global__ void __launch_bounds__(256) pass_l(const float* __restrict__ params, int layer) {
    __shared__ u64 s[4096];
    __shared__ u64 sC[NQ][8];
    int tid = threadIdx.x;
    int l = tid & 31, w = tid >> 5;
    int c = blockIdx.x;  // chunk = g11..g19

    if (tid < NQ) compute_U(params + layer * 63 + tid * 3, sC[tid]);

    u64 a[16];
#pragma unroll
    for (int r = 0; r < 16; ++r) {
        int v = l | (r << 5) | (w << 9);
        int g = (v & 0x7FF) | (c << 11) | ((v >> 11) << 20);
        a[r] = g_psi[g];
    }
    __syncthreads();

    // lane bits v0..v4 -> wires 20..16
    lane_gate(a, l, 0, sC[20]);
    lane_gate(a, l, 1, sC[19]);
    lane_gate(a, l, 2, sC[18]);
    lane_gate(a, l, 3, sC[17]);
    lane_gate(a, l, 4, sC[16]);
    // reg bits v5..v8 -> wires 15..12
    reg_gate<0>(a, sC[15]);
    reg_gate<1>(a, sC[14]);
    reg_gate<2>(a, sC[13]);
    reg_gate<3>(a, sC[12]);

#pragma unroll
    for (int r = 0; r < 16; ++r) s[l | (r << 5) | (w << 9)] = a[r];
    __syncthreads();
#pragma unroll
    for (int r = 0; r < 16; ++r) a[r] = s[l | (w << 5) | (r << 8)];

    // v9,v10 -> wires 11,10 ; v11 (g20) is a passenger
    reg_gate<1>(a, sC[11]);
    reg_gate<2>(a, sC[10]);

    int K = (c & 1) ? 0x7FF : 0;
#pragma unroll
    for (int r = 0; r < 16; ++r) {
        int v = l | (w << 5) | (r << 8);
        int u = v & 0x7FF;
        int x = u;
        x ^= x >> 1; x ^= x >> 2; x ^= x >> 4; x ^= x >> 8;
        int low = x ^ K;
        int wv = low | ((((v >> 11) ^ low) & 1) << 11);
        int g = (wv & 0x7FF) | (c << 11) | ((wv >> 11) << 20);
        g_psi[g] = a[r];
    }
}

// ---------- final pass: layer-3 rotations on wires 10..20 + Z measurement ----------
// Tile: v0..v11 -> g0..g11 (contiguous). chunk = g12..g20.
__global__ void __launch_bounds__(256) pass_f(const float* __restrict__ params) {
    __shared__ u64 s[4096];
    __shared__ u64 sC[NQ][8];
    __shared__ float red[13];
    int tid = threadIdx.x;
    int l = tid & 31, w = tid >> 5;
    int c = blockIdx.x;

    if (tid < NQ) compute_U(params + 3 * 63 + tid * 3, sC[tid]);
    if (tid < 13) red[tid] = 0.0f;

    u64 a[16];
#pragma unroll
    for (int r = 0; r < 16; ++r) {
        int v = l | (r << 5) | (w << 9);
        a[r] = g_psi[v | (c << 12)];
    }
    __syncthreads();

    lane_gate(a, l, 0, sC[20]);
    lane_gate(a, l, 1, sC[19]);
    lane_gate(a, l, 2, sC[18]);
    lane_gate(a, l, 3, sC[17]);
    lane_gate(a, l, 4, sC[16]);
    reg_gate<0>(a, sC[15]);
    reg_gate<1>(a, sC[14]);
    reg_gate<2>(a, sC[13]);
    reg_gate<3>(a, sC[12]);

#pragma unroll
    for (int r = 0; r < 16; ++r) s[l | (r << 5) | (w << 9)] = a[r];
    __syncthreads();
#pragma unroll
    for (int r = 0; r < 16; ++r) a[r] = s[l | (w << 5) | (r << 8)];

    reg_gate<1>(a, sC[11]);  // v9 -> wire 11
    reg_gate<2>(a, sC[10]);  // v10 -> wire 10
    // v11 (g11, wire 9) already rotated in pass H3

    // measurement: v = l | (w<<5) | (r<<8); reg covers v bits 8..11
    float S = 0.0f, a8 = 0.0f, a9 = 0.0f, a10 = 0.0f, a11 = 0.0f;
#pragma unroll
    for (int r = 0; r < 16; ++r) {
        float re, im; unpack2(a[r], re, im);
        float m = fmaf(re, re, im * im);
        S += m;
        a8  += (r & 1) ? -m : m;
        a9  += (r & 2) ? -m : m;
        a10 += (r & 4) ? -m : m;
        a11 += (r & 8) ? -m : m;
    }
    int tb = l | (w << 5);  // v bits 0..7 fixed per thread
    float vals[13];
#pragma unroll
    for (int b = 0; b < 8; ++b) vals[b] = ((tb >> b) & 1) ? -S : S;
    vals[8] = a8; vals[9] = a9; vals[10] = a10; vals[11] = a11; vals[12] = S;
#pragma unroll
    for (int k = 0; k < 13; ++k) {
        float v = vals[k];
#pragma unroll
        for (int o = 16; o > 0; o >>= 1) v += __shfl_down_sync(0xffffffffu, v, o);
        if (l == 0) atomicAdd(&red[k], v);
    }
    __syncthreads();

    if (tid == 0) {
        float Sb = red[12];
        atomicAdd(&g_S, Sb);
        // wires 10..20 from v bits 10..0
#pragma unroll
        for (int b = 0; b < 11; ++b) atomicAdd(&g_z[20 - b], red[b]);
        atomicAdd(&g_z[9], red[11]);  // wire 9 from v bit 11
        // wires 0..8 from chunk bits (g(20-q) = chunk bit 8-q)
#pragma unroll
        for (int q = 0; q < 9; ++q)
            atomicAdd(&g_z[q], ((c >> (8 - q)) & 1) ? -Sb : Sb);
    }
}

// ---------- tiny kernels ----------
__global__ void zero_acc() {
    int t = threadIdx.x;
    if (t < NQ) g_z[t] = 0.0f;
    if (t == NQ) g_S = 0.0f;
}

__global__ void head_kernel(const float* __restrict__ w, const float* __restrict__ b,
                            float* __restrict__ out) {
    if (threadIdx.x == 0) {
        float S = g_S;
        float inv = (S > 0.0f) ? (1.0f / S) : 0.0f;
        float meas[NQ];
        for (int q = 0; q < NQ; ++q) meas[q] = g_z[q] * inv;
        float logits[AD];
        float mx = -1e30f;
        for (int a = 0; a < AD; ++a) {
            float t = b[a];
            for (int q = 0; q < NQ; ++q) t = fmaf(w[a * NQ + q], meas[q], t);
            logits[a] = t;
            if (t > mx) mx = t;
        }
        float sum = 0.0f;
        for (int a = 0; a < AD; ++a) {
            float e = expf(logits[a] - mx);
            logits[a] = e;
            sum += e;
        }
        float is = 1.0f / sum;
        for (int a = 0; a < AD; ++a) out[a] = logits[a] * is;
    }
}

// ---------- launch ----------
extern "C" void kernel_launch(void* const* d_in, const int* in_sizes, int n_in,
                              void* d_out, int out_size) {
    const float* state  = (const float*)d_in[0];  // 2^21 float32
    const float* params = (const float*)d_in[1];  // 252 float32
    const float* hw     = (const float*)d_in[2];  // 18*21 float32
    const float* hb     = (const float*)d_in[3];  // 18 float32
    float* out = (float*)d_out;

    zero_acc<<<1, 32>>>();
    pass_h<<<512, 256>>>(params, state, 0, 1, 1);
    pass_l<<<512, 256>>>(params, 0);
    pass_h<<<512, 256>>>(params, state, 1, 0, 1);
    pass_l<<<512, 256>>>(params, 1);
    pass_h<<<512, 256>>>(params, state, 2, 0, 1);
    pass_l<<<512, 256>>>(params, 2);
    pass_h<<<512, 256>>>(params, state, 3, 0, 0);
    pass_f<<<512, 256>>>(params);
    head_kernel<<<1, 32>>>(hw, hb, out);
}

// round 6
// speedup vs baseline: 1.5604x; 1.0015x over previous
#include <cuda_runtime.h>

#define NQ 21
#define AD 18
#define NSTATE (1 << NQ)

typedef unsigned long long u64;

// 16MB statevector scratch, stored as packed complex: low 32 bits = re, high = im.
static __device__ u64   g_psi[NSTATE];
static __device__ float g_z[NQ];
static __device__ float g_S;

// ---------- packed f32x2 helpers ----------

__device__ __forceinline__ u64 pack2(float lo, float hi) {
    u64 d; asm("mov.b64 %0, {%1,%2};" : "=l"(d) : "f"(lo), "f"(hi)); return d;
}
__device__ __forceinline__ void unpack2(u64 d, float& lo, float& hi) {
    asm("mov.b64 {%0,%1}, %2;" : "=f"(lo), "=f"(hi) : "l"(d));
}
__device__ __forceinline__ u64 dswap(u64 d) {  // (re,im) -> (im,re)
    float lo, hi; unpack2(d, lo, hi); return pack2(hi, lo);
}
__device__ __forceinline__ u64 ffma2(u64 a, u64 b, u64 c) {
    u64 d; asm("fma.rn.f32x2 %0, %1, %2, %3;" : "=l"(d) : "l"(a), "l"(b), "l"(c)); return d;
}
__device__ __forceinline__ u64 fmul2(u64 a, u64 b) {
    u64 d; asm("mul.rn.f32x2 %0, %1, %2;" : "=l"(d) : "l"(a), "l"(b)); return d;
}

__device__ __forceinline__ float2 cmulc(float2 a, float2 b) {
    return make_float2(a.x * b.x - a.y * b.y, a.x * b.y + a.y * b.x);
}

// U = RZ(g)*RY(b)*RX(a); packed coeffs: for element E: (E.x,E.x), (-E.y,E.y).
// C[0..1]=U00, C[2..3]=U01, C[4..5]=U10, C[6..7]=U11
__device__ void compute_U(const float* p, u64* C) {
    float sx, cx, sy, cy, sz, cz;
    sincosf(0.5f * p[0], &sx, &cx);
    sincosf(0.5f * p[1], &sy, &cy);
    sincosf(0.5f * p[2], &sz, &cz);
    float2 m00 = make_float2( cy * cx,  sy * sx);
    float2 m01 = make_float2(-sy * cx, -cy * sx);
    float2 m10 = make_float2( sy * cx, -cy * sx);
    float2 m11 = make_float2( cy * cx, -sy * sx);
    float2 ezm = make_float2(cz, -sz), ezp = make_float2(cz, sz);
    float2 U0 = cmulc(ezm, m00), U1 = cmulc(ezm, m01);
    float2 U2 = cmulc(ezp, m10), U3 = cmulc(ezp, m11);
    C[0] = pack2(U0.x, U0.x); C[1] = pack2(-U0.y, U0.y);
    C[2] = pack2(U1.x, U1.x); C[3] = pack2(-U1.y, U1.y);
    C[4] = pack2(U2.x, U2.x); C[5] = pack2(-U2.y, U2.y);
    C[6] = pack2(U3.x, U3.x); C[7] = pack2(-U3.y, U3.y);
}

// Gate on register bit J: pairs (r, r^(1<<J)) within the 16-amp register file.
template<int J>
__device__ __forceinline__ void reg_gate(u64* a, const u64* C) {
    u64 c0 = C[0], c1 = C[1], c2 = C[2], c3 = C[3];
    u64 c4 = C[4], c5 = C[5], c6 = C[6], c7 = C[7];
#pragma unroll
    for (int r = 0; r < 16; ++r) {
        if (!(r & (1 << J))) {
            u64 x0 = a[r], x1 = a[r ^ (1 << J)];
            u64 s0 = dswap(x0), s1 = dswap(x1);
            a[r]            = ffma2(c0, x0, ffma2(c1, s0, ffma2(c2, x1, fmul2(c3, s1))));
            a[r ^ (1 << J)] = ffma2(c4, x0, ffma2(c5, s0, ffma2(c6, x1, fmul2(c7, s1))));
        }
    }
}

// Gate on lane bit k via shfl_xor. Each lane computes its own new amp:
// bit==0: out = U00*x + U01*p ; bit==1: out = U10*p + U11*x.
__device__ __forceinline__ void lane_gate(u64* a, int l, int k, const u64* C) {
    int bit = (l >> k) & 1;
    u64 d0 = bit ? C[6] : C[0];   // coeff of own amp
    u64 d1 = bit ? C[7] : C[1];
    u64 d2 = bit ? C[4] : C[2];   // coeff of partner amp
    u64 d3 = bit ? C[5] : C[3];
#pragma unroll
    for (int r = 0; r < 16; ++r) {
        u64 p = __shfl_xor_sync(0xffffffffu, a[r], 1 << k);
        a[r] = ffma2(d0, a[r], ffma2(d1, dswap(a[r]), ffma2(d2, p, fmul2(d3, dswap(p)))));
    }
}

// ---------- pass H: local bits v0,v1 -> g0,g1 ; v2..v11 -> g11..g20 ----------
// Rotations on wires 0..9 (g20..g11). CNOT chain (wires 0->1 .. 8->9) folded
// into the store address (suffix-XOR on v bits 2..10).
__global__ void __launch_bounds__(256) pass_h(const float* __restrict__ params,
                                              const float* __restrict__ state_in,
                                              int layer, int first, int do_cnot) {
    __shared__ u64 s[4096];
    __shared__ u64 sC[NQ][8];
    int tid = threadIdx.x;
    int l = tid & 31, w = tid >> 5;
    int c = blockIdx.x;  // chunk = g2..g10

    if (tid < NQ) compute_U(params + layer * 63 + tid * 3, sC[tid]);

    u64 a[16];
    // phase-1 mapping: v = l | (r<<5) | (w<<9)
    if (first) {
#pragma unroll
        for (int r = 0; r < 16; ++r) {
            int v = l | (r << 5) | (w << 9);
            int g = (v & 3) | (c << 2) | ((v >> 2) << 11);
            a[r] = pack2(state_in[g], 0.0f);
        }
    } else {
#pragma unroll
        for (int r = 0; r < 16; ++r) {
            int v = l | (r << 5) | (w << 9);
            int g = (v & 3) | (c << 2) | ((v >> 2) << 11);
            a[r] = g_psi[g];
        }
    }
    __syncthreads();  // sC ready

    // lane bits v2,v3,v4 -> g11,g12,g13 -> wires 9,8,7
    lane_gate(a, l, 2, sC[9]);
    lane_gate(a, l, 3, sC[8]);
    lane_gate(a, l, 4, sC[7]);
    // reg bits (v5..v8) -> g14..g17 -> wires 6,5,4,3
    reg_gate<0>(a, sC[6]);
    reg_gate<1>(a, sC[5]);
    reg_gate<2>(a, sC[4]);
    reg_gate<3>(a, sC[3]);

    // exchange: reg bits now cover v8..v11, warp bits cover v5..v7
#pragma unroll
    for (int r = 0; r < 16; ++r) s[l | (r << 5) | (w << 9)] = a[r];
    __syncthreads();
#pragma unroll
    for (int r = 0; r < 16; ++r) a[r] = s[l | (w << 5) | (r << 8)];

    // reg bits 1,2,3 -> v9,v10,v11 -> g18,g19,g20 -> wires 2,1,0
    reg_gate<1>(a, sC[2]);
    reg_gate<2>(a, sC[1]);
    reg_gate<3>(a, sC[0]);

    // store with CNOT-chain permutation on v bits 2..10
#pragma unroll
    for (int r = 0; r < 16; ++r) {
        int v = l | (w << 5) | (r << 8);
        int wv = v;
        if (do_cnot) {
            int x = v;
            x ^= x >> 1; x ^= x >> 2; x ^= x >> 4; x ^= x >> 8;
            wv = (v & ~0x7FC) | (x & 0x7FC);
        }
        int g = (wv & 3) | (c << 2) | ((wv >> 2) << 11);
        g_psi[g] = a[r];
    }
}

// ---------- pass L: local bits v0..v10 -> g0..g10 ; v11 -> g20 ----------
// Rotations on wires 10..20 (g10..g0). CNOTs (9->10 .. 19->20) + wrap (20->0)
// folded into the store address. Control g11 = chunk bit 0 (classical).
__global__ void __launch_bounds__(256) pass_l(const float* __restrict__ params, int layer) {
    __shared__ u64 s[4096];
    __shared__ u64 sC[NQ][8];
    int tid = threadIdx.x;
    int l = tid & 31, w = tid >> 5;
    int c = blockIdx.x;  // chunk = g11..g19

    if (tid < NQ) compute_U(params + layer * 63 + tid * 3, sC[tid]);

    u64 a[16];
#pragma unroll
    for (int r = 0; r < 16; ++r) {
        int v = l | (r << 5) | (w << 9);
        int g = (v & 0x7FF) | (c << 11) | ((v >> 11) << 20);
        a[r] = g_psi[g];
    }
    __syncthreads();

    // lane bits v0..v4 -> wires 20..16
    lane_gate(a, l, 0, sC[20]);
    lane_gate(a, l, 1, sC[19]);
    lane_gate(a, l, 2, sC[18]);
    lane_gate(a, l, 3, sC[17]);
    lane_gate(a, l, 4, sC[16]);
    // reg bits v5..v8 -> wires 15..12
    reg_gate<0>(a, sC[15]);
    reg_gate<1>(a, sC[14]);
    reg_gate<2>(a, sC[13]);
    reg_gate<3>(a, sC[12]);

#pragma unroll
    for (int r = 0; r < 16; ++r) s[l | (r << 5) | (w << 9)] = a[r];
    __syncthreads();
#pragma unroll
    for (int r = 0; r < 16; ++r) a[r] = s[l | (w << 5) | (r << 8)];

    // v9,v10 -> wires 11,10 ; v11 (g20) is a passenger
    reg_gate<1>(a, sC[11]);
    reg_gate<2>(a, sC[10]);

    int K = (c & 1) ? 0x7FF : 0;
#pragma unroll
    for (int r = 0; r < 16; ++r) {
        int v = l | (w << 5) | (r << 8);
        int u = v & 0x7FF;
        int x = u;
        x ^= x >> 1; x ^= x >> 2; x ^= x >> 4; x ^= x >> 8;
        int low = x ^ K;
        int wv = low | ((((v >> 11) ^ low) & 1) << 11);
        int g = (wv & 0x7FF) | (c << 11) | ((wv >> 11) << 20);
        g_psi[g] = a[r];
    }
}

// ---------- final pass: layer-3 rotations on wires 10..20 + Z measurement ----------
// Tile: v0..v11 -> g0..g11 (contiguous). chunk = g12..g20.
__global__ void __launch_bounds__(256) pass_f(const float* __restrict__ params) {
    __shared__ u64 s[4096];
    __shared__ u64 sC[NQ][8];
    __shared__ float red[13];
    int tid = threadIdx.x;
    int l = tid & 31, w = tid >> 5;
    int c = blockIdx.x;

    if (tid < NQ) compute_U(params + 3 * 63 + tid * 3, sC[tid]);
    if (tid < 13) red[tid] = 0.0f;

    u64 a[16];
#pragma unroll
    for (int r = 0; r < 16; ++r) {
        int v = l | (r << 5) | (w << 9);
        a[r] = g_psi[v | (c << 12)];
    }
    __syncthreads();

    lane_gate(a, l, 0, sC[20]);
    lane_gate(a, l, 1, sC[19]);
    lane_gate(a, l, 2, sC[18]);
    lane_gate(a, l, 3, sC[17]);
    lane_gate(a, l, 4, sC[16]);
    reg_gate<0>(a, sC[15]);
    reg_gate<1>(a, sC[14]);
    reg_gate<2>(a, sC[13]);
    reg_gate<3>(a, sC[12]);

#pragma unroll
    for (int r = 0; r < 16; ++r) s[l | (r << 5) | (w << 9)] = a[r];
    __syncthreads();
#pragma unroll
    for (int r = 0; r < 16; ++r) a[r] = s[l | (w << 5) | (r << 8)];

    reg_gate<1>(a, sC[11]);  // v9 -> wire 11
    reg_gate<2>(a, sC[10]);  // v10 -> wire 10
    // v11 (g11, wire 9) already rotated in pass H3

    // measurement: v = l | (w<<5) | (r<<8); reg covers v bits 8..11
    float S = 0.0f, a8 = 0.0f, a9 = 0.0f, a10 = 0.0f, a11 = 0.0f;
#pragma unroll
    for (int r = 0; r < 16; ++r) {
        float re, im; unpack2(a[r], re, im);
        float m = fmaf(re, re, im * im);
        S += m;
        a8  += (r & 1) ? -m : m;
        a9  += (r & 2) ? -m : m;
        a10 += (r & 4) ? -m : m;
        a11 += (r & 8) ? -m : m;
    }
    int tb = l | (w << 5);  // v bits 0..7 fixed per thread
    float vals[13];
#pragma unroll
    for (int b = 0; b < 8; ++b) vals[b] = ((tb >> b) & 1) ? -S : S;
    vals[8] = a8; vals[9] = a9; vals[10] = a10; vals[11] = a11; vals[12] = S;
#pragma unroll
    for (int k = 0; k < 13; ++k) {
        float v = vals[k];
#pragma unroll
        for (int o = 16; o > 0; o >>= 1) v += __shfl_down_sync(0xffffffffu, v, o);
        if (l == 0) atomicAdd(&red[k], v);
    }
    __syncthreads();

    if (tid == 0) {
        float Sb = red[12];
        atomicAdd(&g_S, Sb);
        // wires 10..20 from v bits 10..0
#pragma unroll
        for (int b = 0; b < 11; ++b) atomicAdd(&g_z[20 - b], red[b]);
        atomicAdd(&g_z[9], red[11]);  // wire 9 from v bit 11
        // wires 0..8 from chunk bits (g(20-q) = chunk bit 8-q)
#pragma unroll
        for (int q = 0; q < 9; ++q)
            atomicAdd(&g_z[q], ((c >> (8 - q)) & 1) ? -Sb : Sb);
    }
}

// ---------- tiny kernels ----------
__global__ void zero_acc() {
    int t = threadIdx.x;
    if (t < NQ) g_z[t] = 0.0f;
    if (t == NQ) g_S = 0.0f;
}

__global__ void head_kernel(const float* __restrict__ w, const float* __restrict__ b,
                            float* __restrict__ out) {
    if (threadIdx.x == 0) {
        float S = g_S;
        float inv = (S > 0.0f) ? (1.0f / S) : 0.0f;
        float meas[NQ];
        for (int q = 0; q < NQ; ++q) meas[q] = g_z[q] * inv;
        float logits[AD];
        float mx = -1e30f;
        for (int a = 0; a < AD; ++a) {
            float t = b[a];
            for (int q = 0; q < NQ; ++q) t = fmaf(w[a * NQ + q], meas[q], t);
            logits[a] = t;
            if (t > mx) mx = t;
        }
        float sum = 0.0f;
        for (int a = 0; a < AD; ++a) {
            float e = expf(logits[a] - mx);
            logits[a] = e;
            sum += e;
        }
        float is = 1.0f / sum;
        for (int a = 0; a < AD; ++a) out[a] = logits[a] * is;
    }
}

// ---------- launch ----------
extern "C" void kernel_launch(void* const* d_in, const int* in_sizes, int n_in,
                              void* d_out, int out_size) {
    const float* state  = (const float*)d_in[0];  // 2^21 float32
    const float* params = (const float*)d_in[1];  // 252 float32
    const float* hw     = (const float*)d_in[2];  // 18*21 float32
    const float* hb     = (const float*)d_in[3];  // 18 float32
    float* out = (float*)d_out;

    zero_acc<<<1, 32>>>();
    pass_h<<<512, 256>>>(params, state, 0, 1, 1);
    pass_l<<<512, 256>>>(params, 0);
    pass_h<<<512, 256>>>(params, state, 1, 0, 1);
    pass_l<<<512, 256>>>(params, 1);
    pass_h<<<512, 256>>>(params, state, 2, 0, 1);
    pass_l<<<512, 256>>>(params, 2);
    pass_h<<<512, 256>>>(params, state, 3, 0, 0);
    pass_f<<<512, 256>>>(params);
    head_kernel<<<1, 32>>>(hw, hb, out);
}